// round 7
// baseline (speedup 1.0000x reference)
#include <cuda_runtime.h>
#include <cuda_fp16.h>
#include <math.h>
#include <cstdint>

#define CDIM 160
#define HW 12544
#define WIMG 112
#define NIMG 32
#define NTHREADS 256
#define TILE_PX 64
#define TILES_PER_CTA 7
#define NBLOCKS 896          // 896 * 7 * 64px = 32*12544 px

#define PA 168      // A smem pitch (fp16) -> conflict-free ldmatrix
#define PB 72       // B smem pitch (fp16) -> conflict-free ldmatrix.trans
#define BSIZE (CDIM * PB * 2)   // 23040 bytes, one B tile

// shared memory byte offsets
#define SM_BIAS  0
#define SM_SCALE 640
#define SM_SHIFT 1280
#define SM_A     2048                       // 160*168*2 = 53760
#define SM_B0    (SM_A + CDIM * PA * 2)     // 55808
#define SM_B1    (SM_B0 + BSIZE)            // 78848
#define SM_TOTAL (SM_B1 + BSIZE)            // 101888 (2 CTAs/SM)

// intermediate y, channel-major [b][c][hw], fp16
__device__ __half g_yh[(size_t)NIMG * CDIM * HW];

// ---------------------------------------------------------------------------
__device__ __forceinline__ uint32_t smem_u32(const void* p) {
    uint32_t a;
    asm("{ .reg .u64 t; cvta.to.shared.u64 t, %1; cvt.u32.u64 %0, t; }" : "=r"(a) : "l"(p));
    return a;
}
__device__ __forceinline__ void ldsm_x4(uint32_t* r, uint32_t addr) {
    asm volatile("ldmatrix.sync.aligned.m8n8.x4.shared.b16 {%0,%1,%2,%3}, [%4];"
        : "=r"(r[0]), "=r"(r[1]), "=r"(r[2]), "=r"(r[3]) : "r"(addr));
}
__device__ __forceinline__ void ldsm_x4t(uint32_t* r, uint32_t addr) {
    asm volatile("ldmatrix.sync.aligned.m8n8.x4.trans.shared.b16 {%0,%1,%2,%3}, [%4];"
        : "=r"(r[0]), "=r"(r[1]), "=r"(r[2]), "=r"(r[3]) : "r"(addr));
}
__device__ __forceinline__ void mma16816(float* d, const uint32_t* a, const uint32_t* b) {
    asm volatile("mma.sync.aligned.m16n8k16.row.col.f32.f16.f16.f32 "
        "{%0,%1,%2,%3}, {%4,%5,%6,%7}, {%8,%9}, {%0,%1,%2,%3};"
        : "+f"(d[0]), "+f"(d[1]), "+f"(d[2]), "+f"(d[3])
        : "r"(a[0]), "r"(a[1]), "r"(a[2]), "r"(a[3]), "r"(b[0]), "r"(b[1]));
}

// ---------------------------------------------------------------------------
// 1-pass fp16 MMA over a 160(ch) x 64(px) tile. 8 warps: 2M x 4N.
// ---------------------------------------------------------------------------
__device__ __forceinline__ void mma_tile(uint32_t sb, uint32_t bufbase,
                                         float acc[5][2][4], int wid, int lane) {
    const int wm = wid >> 2, wn = wid & 3;
    const uint32_t a_lane = (uint32_t)((wm * 80 + (lane & 15)) * (PA * 2) + (lane >> 4) * 16);
    const uint32_t b_lane = (uint32_t)((lane & 15) * (PB * 2) + (wn * 16 + (lane >> 4) * 8) * 2);
    const uint32_t Ab = sb + SM_A + a_lane;
    const uint32_t Bb = sb + bufbase + b_lane;

#pragma unroll
    for (int k0 = 0; k0 < CDIM; k0 += 16) {
        uint32_t a[5][4];
#pragma unroll
        for (int mi = 0; mi < 5; ++mi)
            ldsm_x4(a[mi], Ab + mi * 16 * (PA * 2) + k0 * 2);
        uint32_t b[4];
        ldsm_x4t(b, Bb + k0 * (PB * 2));
#pragma unroll
        for (int mi = 0; mi < 5; ++mi) {
            mma16816(acc[mi][0], a[mi], b);
            mma16816(acc[mi][1], a[mi], b + 2);
        }
    }
}

// ---------------------------------------------------------------------------
// Kernel 1: y = fp16( W_cat @ gelu(bn(x)) + b_cat )
// Each warp owns k-range [wid*20, wid*20+20), each lane a 2-px pair.
// ---------------------------------------------------------------------------
__global__ __launch_bounds__(NTHREADS, 2) void gemm1_mma(
    const float* __restrict__ x,
    const float* __restrict__ gamma, const float* __restrict__ beta,
    const float* __restrict__ rmean, const float* __restrict__ rvar,
    const float* __restrict__ Wt, const float* __restrict__ bt,
    const float* __restrict__ Wb, const float* __restrict__ bb,
    const float* __restrict__ Wr, const float* __restrict__ br,
    const float* __restrict__ Wl, const float* __restrict__ bl,
    const float* __restrict__ Wc, const float* __restrict__ bc) {
    extern __shared__ char smem[];
    const uint32_t sb = smem_u32(smem);
    const int tid = threadIdx.x;
    const int wid = tid >> 5, lane = tid & 31;
    float* bias_s  = (float*)(smem + SM_BIAS);
    float* scale_s = (float*)(smem + SM_SCALE);
    float* shift_s = (float*)(smem + SM_SHIFT);
    __half* Aw = (__half*)(smem + SM_A);

    const float* Wseg[5] = {Wt, Wb, Wr, Wl, Wc};
    for (int idx = tid; idx < CDIM * CDIM; idx += NTHREADS) {
        int m = idx / CDIM;
        int k = idx - m * CDIM;
        Aw[m * PA + k] = __float2half_rn(Wseg[m >> 5][(m & 31) * CDIM + k]);
    }
    if (tid < CDIM) {
        const float* bp[5] = {bt, bb, br, bl, bc};
        bias_s[tid] = bp[tid >> 5][tid & 31];
        float s = gamma[tid] * rsqrtf(rvar[tid] + 1e-5f);
        scale_s[tid] = s;
        shift_s[tid] = beta[tid] - rmean[tid] * s;
    }
    __syncthreads();

    const int pxp = (lane) * 2;          // 2-px pair within tile
    const int kbase = wid * 20;          // 20 k-channels per warp
    const int wm = wid >> 2, wn = wid & 3;
    const int tr = lane >> 2, tc = 2 * (lane & 3);

    float2 v[20];

    auto issue_loads = [&](int tile) {
        const int b = (tile * TILE_PX) / HW;
        const int p0 = tile * TILE_PX - b * HW;
        const float* xb = x + (size_t)b * CDIM * HW + p0 + pxp;
#pragma unroll
        for (int j = 0; j < 20; ++j)
            v[j] = __ldg((const float2*)(xb + (size_t)(kbase + j) * HW));
    };
    auto do_conv = [&](char* buf) {
#pragma unroll
        for (int j = 0; j < 20; ++j) {
            const int k = kbase + j;
            float h0 = fmaf(v[j].x, scale_s[k], shift_s[k]);
            float h1 = fmaf(v[j].y, scale_s[k], shift_s[k]);
            float g0 = 0.5f * h0 * (1.0f + erff(h0 * 0.70710678118654752f));
            float g1 = 0.5f * h1 * (1.0f + erff(h1 * 0.70710678118654752f));
            __half2 hv = __floats2half2_rn(g0, g1);
            *(__half2*)((__half*)buf + k * PB + pxp) = hv;
        }
    };

    // prologue: prep tile 0 into buf0
    issue_loads(blockIdx.x * TILES_PER_CTA);
    do_conv(smem + SM_B0);
    __syncthreads();

    for (int t = 0; t < TILES_PER_CTA; ++t) {
        const int tile = blockIdx.x * TILES_PER_CTA + t;
        const int b = (tile * TILE_PX) / HW;
        const int p0 = tile * TILE_PX - b * HW;
        const uint32_t curbuf = (t & 1) ? SM_B1 : SM_B0;
        char* nxtbuf = smem + ((t & 1) ? SM_B0 : SM_B1);

        // ALL t+1 loads in flight before MMA
        if (t + 1 < TILES_PER_CTA) issue_loads(tile + 1);

        float acc[5][2][4] = {};
        mma_tile(sb, curbuf, acc, wid, lane);

        // conversion: data already landed under MMA
        if (t + 1 < TILES_PER_CTA) do_conv(nxtbuf);

        // epilogue: +bias -> fp16, packed 2-px stores
        __half* yb = g_yh + (size_t)b * CDIM * HW + p0;
#pragma unroll
        for (int mi = 0; mi < 5; ++mi) {
            const int r0 = wm * 80 + mi * 16 + tr;
            const float bia0 = bias_s[r0];
            const float bia1 = bias_s[r0 + 8];
#pragma unroll
            for (int ni = 0; ni < 2; ++ni) {
                const int c = wn * 16 + ni * 8 + tc;
                *(__half2*)(yb + (size_t)r0 * HW + c) =
                    __floats2half2_rn(acc[mi][ni][0] + bia0, acc[mi][ni][1] + bia0);
                *(__half2*)(yb + (size_t)(r0 + 8) * HW + c) =
                    __floats2half2_rn(acc[mi][ni][2] + bia1, acc[mi][ni][3] + bia1);
            }
        }
        __syncthreads();
    }
}

// ---------------------------------------------------------------------------
// Kernel 2: out = W_fuse @ shifted_gather(y) + b_fuse
// ---------------------------------------------------------------------------
__global__ __launch_bounds__(NTHREADS, 2) void gemm2_mma(
    const float* __restrict__ Wf, const float* __restrict__ bf,
    float* __restrict__ out) {
    extern __shared__ char smem[];
    const uint32_t sb = smem_u32(smem);
    const int tid = threadIdx.x;
    const int wid = tid >> 5, lane = tid & 31;
    float* bias_s = (float*)(smem + SM_BIAS);
    __half* Aw = (__half*)(smem + SM_A);

    for (int idx = tid; idx < CDIM * CDIM; idx += NTHREADS) {
        int m = idx / CDIM;
        int k = idx - m * CDIM;
        Aw[m * PA + k] = __float2half_rn(Wf[m * CDIM + k]);
    }
    if (tid < CDIM) bias_s[tid] = bf[tid];
    __syncthreads();

    const int pxp = lane * 2;
    const int kbase = wid * 20;
    const int wm = wid >> 2, wn = wid & 3;
    const int tr = lane >> 2, tc = 2 * (lane & 3);

    uint32_t vv[20];

    // packed 2-px shifted gather, all loads independent
    auto issue_gather = [&](int tile) {
        const int b = (tile * TILE_PX) / HW;
        const int p0 = tile * TILE_PX - b * HW;
        const __half* yb = g_yh + (size_t)b * CDIM * HW;
        const int p = p0 + pxp;              // even
        const int hr = p / WIMG;
        const int w = p - hr * WIMG;         // even
#pragma unroll
        for (int j = 0; j < 20; ++j) {
            const int k = kbase + j;
            const int seg = k >> 5;
            const __half* base = yb + (size_t)k * HW;
            uint32_t r;
            if (seg == 0) {          // shift up: y[p+112..p+113]
                r = (hr < WIMG - 1) ? __ldg((const uint32_t*)(base + p + WIMG)) : 0u;
            } else if (seg == 1) {   // shift down: y[p-112..p-111]
                r = (hr > 0) ? __ldg((const uint32_t*)(base + p - WIMG)) : 0u;
            } else if (seg == 2) {   // shift right: lo=y[p-1] (w>0), hi=y[p]
                uint32_t lo = (w > 0) ? (uint32_t)__ldg((const uint16_t*)(base + p - 1)) : 0u;
                uint32_t hi = (uint32_t)__ldg((const uint16_t*)(base + p));
                r = lo | (hi << 16);
            } else if (seg == 3) {   // shift left: lo=y[p+1], hi=y[p+2] (w<110)
                uint32_t lo = (uint32_t)__ldg((const uint16_t*)(base + p + 1));
                uint32_t hi = (w < WIMG - 2) ? (uint32_t)__ldg((const uint16_t*)(base + p + 2)) : 0u;
                r = lo | (hi << 16);
            } else {                 // center
                r = __ldg((const uint32_t*)(base + p));
            }
            vv[j] = r;
        }
    };
    auto do_conv = [&](char* buf) {
#pragma unroll
        for (int j = 0; j < 20; ++j)
            *(uint32_t*)((__half*)buf + (kbase + j) * PB + pxp) = vv[j];
    };

    issue_gather(blockIdx.x * TILES_PER_CTA);
    do_conv(smem + SM_B0);
    __syncthreads();

    for (int t = 0; t < TILES_PER_CTA; ++t) {
        const int tile = blockIdx.x * TILES_PER_CTA + t;
        const int b = (tile * TILE_PX) / HW;
        const int p0 = tile * TILE_PX - b * HW;
        const uint32_t curbuf = (t & 1) ? SM_B1 : SM_B0;
        char* nxtbuf = smem + ((t & 1) ? SM_B0 : SM_B1);

        if (t + 1 < TILES_PER_CTA) issue_gather(tile + 1);

        float acc[5][2][4] = {};
        mma_tile(sb, curbuf, acc, wid, lane);

        if (t + 1 < TILES_PER_CTA) do_conv(nxtbuf);

        float* ob = out + (size_t)b * CDIM * HW + p0;
#pragma unroll
        for (int mi = 0; mi < 5; ++mi) {
            const int r0 = wm * 80 + mi * 16 + tr;
            const float bia0 = bias_s[r0];
            const float bia1 = bias_s[r0 + 8];
#pragma unroll
            for (int ni = 0; ni < 2; ++ni) {
                const int c = wn * 16 + ni * 8 + tc;
                *(float2*)(ob + (size_t)r0 * HW + c) =
                    make_float2(acc[mi][ni][0] + bia0, acc[mi][ni][1] + bia0);
                *(float2*)(ob + (size_t)(r0 + 8) * HW + c) =
                    make_float2(acc[mi][ni][2] + bia1, acc[mi][ni][3] + bia1);
            }
        }
        __syncthreads();
    }
}

// ---------------------------------------------------------------------------
extern "C" void kernel_launch(void* const* d_in, const int* in_sizes, int n_in,
                              void* d_out, int out_size) {
    const float* x     = (const float*)d_in[0];
    const float* gamma = (const float*)d_in[1];
    const float* beta  = (const float*)d_in[2];
    const float* rmean = (const float*)d_in[3];
    const float* rvar  = (const float*)d_in[4];
    const float* Wt = (const float*)d_in[5];  const float* bt = (const float*)d_in[6];
    const float* Wb = (const float*)d_in[7];  const float* bb = (const float*)d_in[8];
    const float* Wr = (const float*)d_in[9];  const float* br = (const float*)d_in[10];
    const float* Wl = (const float*)d_in[11]; const float* bl = (const float*)d_in[12];
    const float* Wc = (const float*)d_in[13]; const float* bc = (const float*)d_in[14];
    const float* Wf = (const float*)d_in[15]; const float* bf = (const float*)d_in[16];

    cudaFuncSetAttribute(gemm1_mma, cudaFuncAttributeMaxDynamicSharedMemorySize, SM_TOTAL);
    cudaFuncSetAttribute(gemm2_mma, cudaFuncAttributeMaxDynamicSharedMemorySize, SM_TOTAL);

    gemm1_mma<<<NBLOCKS, NTHREADS, SM_TOTAL>>>(x, gamma, beta, rmean, rvar,
                                               Wt, bt, Wb, bb, Wr, br, Wl, bl, Wc, bc);
    gemm2_mma<<<NBLOCKS, NTHREADS, SM_TOTAL>>>(Wf, bf, (float*)d_out);
}

// round 9
// speedup vs baseline: 1.3695x; 1.3695x over previous
#include <cuda_runtime.h>
#include <cuda_fp16.h>
#include <math.h>
#include <cstdint>

#define CDIM 160
#define HW 12544
#define WIMG 112
#define NIMG 32
#define NTHREADS 256
#define TILE_PX 64
#define TILES_PER_CTA 7
#define NBLOCKS 896          // 896 * 7 * 64px = 32*12544 px

#define PA 168      // A smem pitch (fp16) -> conflict-free ldmatrix
#define PB 72       // B smem pitch (fp16) -> conflict-free ldmatrix.trans
#define BSIZE (CDIM * PB * 2)   // 23040 bytes, one B tile

// shared memory byte offsets
#define SM_BIAS  0
#define SM_SCALE 640
#define SM_SHIFT 1280
#define SM_A     2048                       // 160*168*2 = 53760
#define SM_B0    (SM_A + CDIM * PA * 2)     // 55808
#define SM_B1    (SM_B0 + BSIZE)            // 78848
#define SM_TOTAL (SM_B1 + BSIZE)            // 101888 (2 CTAs/SM)

// PRE-SHIFTED intermediate: yt[c][p] = (shifted y)[c][p], channel-major fp16.
// gemm1 scatters y[c][q] -> yt[c][q - delta(seg(c))], borders zeroed explicitly.
__device__ __half g_yt[(size_t)NIMG * CDIM * HW];

// ---------------------------------------------------------------------------
__device__ __forceinline__ uint32_t smem_u32(const void* p) {
    uint32_t a;
    asm("{ .reg .u64 t; cvta.to.shared.u64 t, %1; cvt.u32.u64 %0, t; }" : "=r"(a) : "l"(p));
    return a;
}
__device__ __forceinline__ void ldsm_x4(uint32_t* r, uint32_t addr) {
    asm volatile("ldmatrix.sync.aligned.m8n8.x4.shared.b16 {%0,%1,%2,%3}, [%4];"
        : "=r"(r[0]), "=r"(r[1]), "=r"(r[2]), "=r"(r[3]) : "r"(addr));
}
__device__ __forceinline__ void ldsm_x4t(uint32_t* r, uint32_t addr) {
    asm volatile("ldmatrix.sync.aligned.m8n8.x4.trans.shared.b16 {%0,%1,%2,%3}, [%4];"
        : "=r"(r[0]), "=r"(r[1]), "=r"(r[2]), "=r"(r[3]) : "r"(addr));
}
__device__ __forceinline__ void mma16816(float* d, const uint32_t* a, const uint32_t* b) {
    asm volatile("mma.sync.aligned.m16n8k16.row.col.f32.f16.f16.f32 "
        "{%0,%1,%2,%3}, {%4,%5,%6,%7}, {%8,%9}, {%0,%1,%2,%3};"
        : "+f"(d[0]), "+f"(d[1]), "+f"(d[2]), "+f"(d[3])
        : "r"(a[0]), "r"(a[1]), "r"(a[2]), "r"(a[3]), "r"(b[0]), "r"(b[1]));
}

// ---------------------------------------------------------------------------
// 1-pass fp16 MMA over a 160(ch) x 64(px) tile. 8 warps: 2M x 4N.
// ---------------------------------------------------------------------------
__device__ __forceinline__ void mma_tile(uint32_t sb, uint32_t bufbase,
                                         float acc[5][2][4], int wid, int lane) {
    const int wm = wid >> 2, wn = wid & 3;
    const uint32_t a_lane = (uint32_t)((wm * 80 + (lane & 15)) * (PA * 2) + (lane >> 4) * 16);
    const uint32_t b_lane = (uint32_t)((lane & 15) * (PB * 2) + (wn * 16 + (lane >> 4) * 8) * 2);
    const uint32_t Ab = sb + SM_A + a_lane;
    const uint32_t Bb = sb + bufbase + b_lane;

#pragma unroll
    for (int k0 = 0; k0 < CDIM; k0 += 16) {
        uint32_t a[5][4];
#pragma unroll
        for (int mi = 0; mi < 5; ++mi)
            ldsm_x4(a[mi], Ab + mi * 16 * (PA * 2) + k0 * 2);
        uint32_t b[4];
        ldsm_x4t(b, Bb + k0 * (PB * 2));
#pragma unroll
        for (int mi = 0; mi < 5; ++mi) {
            mma16816(acc[mi][0], a[mi], b);
            mma16816(acc[mi][1], a[mi], b + 2);
        }
    }
}

// ---------------------------------------------------------------------------
// Kernel 1: yt = scatter_shift( W_cat @ gelu(bn(x)) + b_cat )
// Prep: each thread loads 10 float4 (4px x 1ch) in two batches of 5.
// ---------------------------------------------------------------------------
__global__ __launch_bounds__(NTHREADS, 2) void gemm1_mma(
    const float* __restrict__ x,
    const float* __restrict__ gamma, const float* __restrict__ beta,
    const float* __restrict__ rmean, const float* __restrict__ rvar,
    const float* __restrict__ Wt, const float* __restrict__ bt,
    const float* __restrict__ Wb, const float* __restrict__ bb,
    const float* __restrict__ Wr, const float* __restrict__ br,
    const float* __restrict__ Wl, const float* __restrict__ bl,
    const float* __restrict__ Wc, const float* __restrict__ bc) {
    extern __shared__ char smem[];
    const uint32_t sb = smem_u32(smem);
    const int tid = threadIdx.x;
    const int wid = tid >> 5, lane = tid & 31;
    float* bias_s  = (float*)(smem + SM_BIAS);
    float* scale_s = (float*)(smem + SM_SCALE);
    float* shift_s = (float*)(smem + SM_SHIFT);
    __half* Aw = (__half*)(smem + SM_A);

    const float* Wseg[5] = {Wt, Wb, Wr, Wl, Wc};
    for (int idx = tid; idx < CDIM * CDIM; idx += NTHREADS) {
        int m = idx / CDIM;
        int k = idx - m * CDIM;
        Aw[m * PA + k] = __float2half_rn(Wseg[m >> 5][(m & 31) * CDIM + k]);
    }
    if (tid < CDIM) {
        const float* bp[5] = {bt, bb, br, bl, bc};
        bias_s[tid] = bp[tid >> 5][tid & 31];
        float s = gamma[tid] * rsqrtf(rvar[tid] + 1e-5f);
        scale_s[tid] = s;
        shift_s[tid] = beta[tid] - rmean[tid] * s;
    }
    __syncthreads();

    // prep mapping: chunk = tid&15 (4px each), channels chbase..chbase+9
    const int chunk = tid & 15;
    const int chbase = (tid >> 4) * 10;
    const int wm = wid >> 2, wn = wid & 3;
    const int tr = lane >> 2, tc = 2 * (lane & 3);

    float4 v[5];

    auto issue_batch = [&](int tile, int j0) {
        const int b = (tile * TILE_PX) / HW;
        const int p0 = tile * TILE_PX - b * HW;
        const float* xb = x + (size_t)b * CDIM * HW + p0 + chunk * 4;
#pragma unroll
        for (int j = 0; j < 5; ++j)
            v[j] = __ldg((const float4*)(xb + (size_t)(chbase + j0 + j) * HW));
    };
    auto conv_batch = [&](char* buf, int j0) {
#pragma unroll
        for (int j = 0; j < 5; ++j) {
            const int k = chbase + j0 + j;
            const float sc = scale_s[k], sh = shift_s[k];
            float h0 = fmaf(v[j].x, sc, sh), h1 = fmaf(v[j].y, sc, sh);
            float h2 = fmaf(v[j].z, sc, sh), h3 = fmaf(v[j].w, sc, sh);
            float g0 = 0.5f * h0 * (1.0f + erff(h0 * 0.70710678118654752f));
            float g1 = 0.5f * h1 * (1.0f + erff(h1 * 0.70710678118654752f));
            float g2 = 0.5f * h2 * (1.0f + erff(h2 * 0.70710678118654752f));
            float g3 = 0.5f * h3 * (1.0f + erff(h3 * 0.70710678118654752f));
            __half2 o2[2];
            o2[0] = __floats2half2_rn(g0, g1);
            o2[1] = __floats2half2_rn(g2, g3);
            *(float2*)((__half*)buf + k * PB + chunk * 4) = *(float2*)o2;
        }
    };

    // prologue: tile 0 into buf0
    issue_batch(blockIdx.x * TILES_PER_CTA, 0);
    conv_batch(smem + SM_B0, 0);
    issue_batch(blockIdx.x * TILES_PER_CTA, 5);
    conv_batch(smem + SM_B0, 5);
    __syncthreads();

    for (int t = 0; t < TILES_PER_CTA; ++t) {
        const int tile = blockIdx.x * TILES_PER_CTA + t;
        const int b = (tile * TILE_PX) / HW;
        const int p0 = tile * TILE_PX - b * HW;
        const uint32_t curbuf = (t & 1) ? SM_B1 : SM_B0;
        char* nxtbuf = smem + ((t & 1) ? SM_B0 : SM_B1);
        const bool more = (t + 1 < TILES_PER_CTA);

        // batch 0 of t+1 in flight under MMA
        if (more) issue_batch(tile + 1, 0);

        float acc[5][2][4] = {};
        mma_tile(sb, curbuf, acc, wid, lane);

        if (more) {
            conv_batch(nxtbuf, 0);          // data landed under MMA
            issue_batch(tile + 1, 5);       // batch 1 latency hides under conv+epilogue
        }

        __half* yb = g_yt + (size_t)b * CDIM * HW;

        // border zeroing: threads 0..63 own px c of this tile
        if (tid < TILE_PX) {
            const int q = p0 + tid;
            const int h = q / WIMG;
            const int w = q - h * WIMG;
            const __half z = __ushort_as_half((unsigned short)0);
            if (h == WIMG - 1) { for (int c = 0;  c < 32;  ++c) yb[(size_t)c * HW + q] = z; }
            if (h == 0)        { for (int c = 32; c < 64;  ++c) yb[(size_t)c * HW + q] = z; }
            if (w == 0)        { for (int c = 64; c < 96;  ++c) yb[(size_t)c * HW + q] = z; }
            if (w == WIMG - 1) { for (int c = 96; c < 128; ++c) yb[(size_t)c * HW + q] = z; }
        }

        // epilogue: +bias -> fp16, scatter into pre-shifted yt
#pragma unroll
        for (int mi = 0; mi < 5; ++mi) {
#pragma unroll
            for (int row = 0; row < 2; ++row) {
                const int r = wm * 80 + mi * 16 + tr + row * 8;
                const float bia = bias_s[r];
                const int seg = r >> 5;
                __half* base = yb + (size_t)r * HW;
#pragma unroll
                for (int ni = 0; ni < 2; ++ni) {
                    const int c = wn * 16 + ni * 8 + tc;
                    const int q = p0 + c;
                    const int h = q / WIMG;
                    const int w = q - h * WIMG;
                    const float f0 = acc[mi][ni][row * 2 + 0] + bia;
                    const float f1 = acc[mi][ni][row * 2 + 1] + bia;
                    if (seg == 0) {          // shift up: src(h,w)->tgt(h-1,w)
                        if (h >= 1) *(__half2*)(base + q - WIMG) = __floats2half2_rn(f0, f1);
                    } else if (seg == 1) {   // shift down: ->(h+1,w)
                        if (h <= WIMG - 2) *(__half2*)(base + q + WIMG) = __floats2half2_rn(f0, f1);
                    } else if (seg == 2) {   // shift right: ->(h,w+1)
                        if (w <= WIMG - 2) base[q + 1] = __float2half_rn(f0);
                        if (w <= WIMG - 3) base[q + 2] = __float2half_rn(f1);
                    } else if (seg == 3) {   // shift left: ->(h,w-1)
                        if (w >= 1) base[q - 1] = __float2half_rn(f0);
                        base[q] = __float2half_rn(f1);
                    } else {                 // center
                        *(__half2*)(base + q) = __floats2half2_rn(f0, f1);
                    }
                }
            }
        }
        if (more) conv_batch(nxtbuf, 5);
        __syncthreads();
    }
}

// ---------------------------------------------------------------------------
// Kernel 2: out = W_fuse @ yt + b_fuse   (pure aligned 16B copies for B)
// ---------------------------------------------------------------------------
__global__ __launch_bounds__(NTHREADS, 2) void gemm2_mma(
    const float* __restrict__ Wf, const float* __restrict__ bf,
    float* __restrict__ out) {
    extern __shared__ char smem[];
    const uint32_t sb = smem_u32(smem);
    const int tid = threadIdx.x;
    const int wid = tid >> 5, lane = tid & 31;
    float* bias_s = (float*)(smem + SM_BIAS);
    __half* Aw = (__half*)(smem + SM_A);

    for (int idx = tid; idx < CDIM * CDIM; idx += NTHREADS) {
        int m = idx / CDIM;
        int k = idx - m * CDIM;
        Aw[m * PA + k] = __float2half_rn(Wf[m * CDIM + k]);
    }
    if (tid < CDIM) bias_s[tid] = bf[tid];
    __syncthreads();

    // prep mapping: slot = tid&7 (8px each), channels chbase..chbase+4
    const int slot = tid & 7;
    const int chbase = (tid >> 3) * 5;
    const int wm = wid >> 2, wn = wid & 3;
    const int tr = lane >> 2, tc = 2 * (lane & 3);

    uint4 v[5];

    auto issue_loads = [&](int tile) {
        const int b = (tile * TILE_PX) / HW;
        const int p0 = tile * TILE_PX - b * HW;
        const __half* yb = g_yt + (size_t)b * CDIM * HW + p0 + slot * 8;
#pragma unroll
        for (int j = 0; j < 5; ++j)
            v[j] = __ldg((const uint4*)(yb + (size_t)(chbase + j) * HW));
    };
    auto store_smem = [&](char* buf) {
#pragma unroll
        for (int j = 0; j < 5; ++j)
            *(uint4*)((__half*)buf + (chbase + j) * PB + slot * 8) = v[j];
    };

    issue_loads(blockIdx.x * TILES_PER_CTA);
    store_smem(smem + SM_B0);
    __syncthreads();

    for (int t = 0; t < TILES_PER_CTA; ++t) {
        const int tile = blockIdx.x * TILES_PER_CTA + t;
        const int b = (tile * TILE_PX) / HW;
        const int p0 = tile * TILE_PX - b * HW;
        const uint32_t curbuf = (t & 1) ? SM_B1 : SM_B0;
        char* nxtbuf = smem + ((t & 1) ? SM_B0 : SM_B1);

        if (t + 1 < TILES_PER_CTA) issue_loads(tile + 1);   // in flight under MMA

        float acc[5][2][4] = {};
        mma_tile(sb, curbuf, acc, wid, lane);

        if (t + 1 < TILES_PER_CTA) store_smem(nxtbuf);      // data landed under MMA

        float* ob = out + (size_t)b * CDIM * HW + p0;
#pragma unroll
        for (int mi = 0; mi < 5; ++mi) {
            const int r0 = wm * 80 + mi * 16 + tr;
            const float bia0 = bias_s[r0];
            const float bia1 = bias_s[r0 + 8];
#pragma unroll
            for (int ni = 0; ni < 2; ++ni) {
                const int c = wn * 16 + ni * 8 + tc;
                *(float2*)(ob + (size_t)r0 * HW + c) =
                    make_float2(acc[mi][ni][0] + bia0, acc[mi][ni][1] + bia0);
                *(float2*)(ob + (size_t)(r0 + 8) * HW + c) =
                    make_float2(acc[mi][ni][2] + bia1, acc[mi][ni][3] + bia1);
            }
        }
        __syncthreads();
    }
}

// ---------------------------------------------------------------------------
extern "C" void kernel_launch(void* const* d_in, const int* in_sizes, int n_in,
                              void* d_out, int out_size) {
    const float* x     = (const float*)d_in[0];
    const float* gamma = (const float*)d_in[1];
    const float* beta  = (const float*)d_in[2];
    const float* rmean = (const float*)d_in[3];
    const float* rvar  = (const float*)d_in[4];
    const float* Wt = (const float*)d_in[5];  const float* bt = (const float*)d_in[6];
    const float* Wb = (const float*)d_in[7];  const float* bb = (const float*)d_in[8];
    const float* Wr = (const float*)d_in[9];  const float* br = (const float*)d_in[10];
    const float* Wl = (const float*)d_in[11]; const float* bl = (const float*)d_in[12];
    const float* Wc = (const float*)d_in[13]; const float* bc = (const float*)d_in[14];
    const float* Wf = (const float*)d_in[15]; const float* bf = (const float*)d_in[16];

    cudaFuncSetAttribute(gemm1_mma, cudaFuncAttributeMaxDynamicSharedMemorySize, SM_TOTAL);
    cudaFuncSetAttribute(gemm2_mma, cudaFuncAttributeMaxDynamicSharedMemorySize, SM_TOTAL);

    gemm1_mma<<<NBLOCKS, NTHREADS, SM_TOTAL>>>(x, gamma, beta, rmean, rvar,
                                               Wt, bt, Wb, bb, Wr, br, Wl, bl, Wc, bc);
    gemm2_mma<<<NBLOCKS, NTHREADS, SM_TOTAL>>>(Wf, bf, (float*)d_out);
}

// round 10
// speedup vs baseline: 1.3821x; 1.0092x over previous
#include <cuda_runtime.h>
#include <cuda_fp16.h>
#include <math.h>
#include <cstdint>

#define CDIM 160
#define HW 12544
#define WIMG 112
#define NIMG 32
#define NTHREADS 256
#define TILE_PX 64
#define TILES_PER_CTA 7
#define NBLOCKS 896          // 896 * 7 * 64px = 32*12544 px

#define PA 168      // A smem pitch (fp16) -> conflict-free ldmatrix
#define PB 72       // B smem pitch (fp16) -> conflict-free ldmatrix.trans
#define BSIZE (CDIM * PB * 2)   // 23040 bytes, one B tile

// shared memory byte offsets
#define SM_BIAS  0
#define SM_SCALE 640
#define SM_SHIFT 1280
#define SM_A     2048                       // 160*168*2 = 53760
#define SM_B0    (SM_A + CDIM * PA * 2)     // 55808
#define SM_B1    (SM_B0 + BSIZE)            // 78848
#define SM_TOTAL (SM_B1 + BSIZE)            // 101888 (2 CTAs/SM)

// PRE-SHIFTED intermediate: yt[c][p] = (shifted y)[c][p], channel-major fp16.
__device__ __half g_yt[(size_t)NIMG * CDIM * HW];

// ---------------------------------------------------------------------------
__device__ __forceinline__ uint32_t smem_u32(const void* p) {
    uint32_t a;
    asm("{ .reg .u64 t; cvta.to.shared.u64 t, %1; cvt.u32.u64 %0, t; }" : "=r"(a) : "l"(p));
    return a;
}
__device__ __forceinline__ void ldsm_x4(uint32_t* r, uint32_t addr) {
    asm volatile("ldmatrix.sync.aligned.m8n8.x4.shared.b16 {%0,%1,%2,%3}, [%4];"
        : "=r"(r[0]), "=r"(r[1]), "=r"(r[2]), "=r"(r[3]) : "r"(addr));
}
__device__ __forceinline__ void ldsm_x4t(uint32_t* r, uint32_t addr) {
    asm volatile("ldmatrix.sync.aligned.m8n8.x4.trans.shared.b16 {%0,%1,%2,%3}, [%4];"
        : "=r"(r[0]), "=r"(r[1]), "=r"(r[2]), "=r"(r[3]) : "r"(addr));
}
__device__ __forceinline__ void mma16816(float* d, const uint32_t* a, const uint32_t* b) {
    asm volatile("mma.sync.aligned.m16n8k16.row.col.f32.f16.f16.f32 "
        "{%0,%1,%2,%3}, {%4,%5,%6,%7}, {%8,%9}, {%0,%1,%2,%3};"
        : "+f"(d[0]), "+f"(d[1]), "+f"(d[2]), "+f"(d[3])
        : "r"(a[0]), "r"(a[1]), "r"(a[2]), "r"(a[3]), "r"(b[0]), "r"(b[1]));
}

// fast exact-GELU: erf via Abramowitz-Stegun 7.1.26, |abs err| <= 1.5e-7
__device__ __forceinline__ float fast_gelu(float h) {
    const float x = h * 0.70710678118654752f;
    const float ax = fabsf(x);
    const float t = __fdividef(1.0f, fmaf(0.3275911f, ax, 1.0f));
    float p = fmaf(t, 1.061405429f, -1.453152027f);
    p = fmaf(t, p, 1.421413741f);
    p = fmaf(t, p, -0.284496736f);
    p = fmaf(t, p, 0.254829592f);
    p *= t;
    const float e = __expf(-ax * ax);
    const float erf_abs = fmaf(-p, e, 1.0f);
    const float erf_v = copysignf(erf_abs, x);
    return 0.5f * h * (1.0f + erf_v);
}

// ---------------------------------------------------------------------------
// 1-pass fp16 MMA over a 160(ch) x 64(px) tile. 8 warps: 2M x 4N.
// ---------------------------------------------------------------------------
__device__ __forceinline__ void mma_tile(uint32_t sb, uint32_t bufbase,
                                         float acc[5][2][4], int wid, int lane) {
    const int wm = wid >> 2, wn = wid & 3;
    const uint32_t a_lane = (uint32_t)((wm * 80 + (lane & 15)) * (PA * 2) + (lane >> 4) * 16);
    const uint32_t b_lane = (uint32_t)((lane & 15) * (PB * 2) + (wn * 16 + (lane >> 4) * 8) * 2);
    const uint32_t Ab = sb + SM_A + a_lane;
    const uint32_t Bb = sb + bufbase + b_lane;

#pragma unroll
    for (int k0 = 0; k0 < CDIM; k0 += 16) {
        uint32_t a[5][4];
#pragma unroll
        for (int mi = 0; mi < 5; ++mi)
            ldsm_x4(a[mi], Ab + mi * 16 * (PA * 2) + k0 * 2);
        uint32_t b[4];
        ldsm_x4t(b, Bb + k0 * (PB * 2));
#pragma unroll
        for (int mi = 0; mi < 5; ++mi) {
            mma16816(acc[mi][0], a[mi], b);
            mma16816(acc[mi][1], a[mi], b + 2);
        }
    }
}

// ---------------------------------------------------------------------------
// Kernel 1: yt = scatter_shift( W_cat @ gelu(bn(x)) + b_cat )
// ---------------------------------------------------------------------------
__global__ __launch_bounds__(NTHREADS, 2) void gemm1_mma(
    const float* __restrict__ x,
    const float* __restrict__ gamma, const float* __restrict__ beta,
    const float* __restrict__ rmean, const float* __restrict__ rvar,
    const float* __restrict__ Wt, const float* __restrict__ bt,
    const float* __restrict__ Wb, const float* __restrict__ bb,
    const float* __restrict__ Wr, const float* __restrict__ br,
    const float* __restrict__ Wl, const float* __restrict__ bl,
    const float* __restrict__ Wc, const float* __restrict__ bc) {
    extern __shared__ char smem[];
    const uint32_t sb = smem_u32(smem);
    const int tid = threadIdx.x;
    const int wid = tid >> 5, lane = tid & 31;
    float* bias_s  = (float*)(smem + SM_BIAS);
    float* scale_s = (float*)(smem + SM_SCALE);
    float* shift_s = (float*)(smem + SM_SHIFT);
    __half* Aw = (__half*)(smem + SM_A);

    const float* Wseg[5] = {Wt, Wb, Wr, Wl, Wc};
    for (int idx = tid; idx < CDIM * CDIM; idx += NTHREADS) {
        int m = idx / CDIM;
        int k = idx - m * CDIM;
        Aw[m * PA + k] = __float2half_rn(Wseg[m >> 5][(m & 31) * CDIM + k]);
    }
    if (tid < CDIM) {
        const float* bp[5] = {bt, bb, br, bl, bc};
        bias_s[tid] = bp[tid >> 5][tid & 31];
        float s = gamma[tid] * rsqrtf(rvar[tid] + 1e-5f);
        scale_s[tid] = s;
        shift_s[tid] = beta[tid] - rmean[tid] * s;
    }
    __syncthreads();

    // prep mapping: chunk = tid&15 (4px each), channels chbase..chbase+9
    const int chunk = tid & 15;
    const int chbase = (tid >> 4) * 10;
    const int wm = wid >> 2, wn = wid & 3;
    const int tr = lane >> 2, tc = 2 * (lane & 3);

    float4 v[5];

    auto issue_batch = [&](int tile, int j0) {
        const int b = (tile * TILE_PX) / HW;
        const int p0 = tile * TILE_PX - b * HW;
        const float* xb = x + (size_t)b * CDIM * HW + p0 + chunk * 4;
#pragma unroll
        for (int j = 0; j < 5; ++j)
            v[j] = __ldg((const float4*)(xb + (size_t)(chbase + j0 + j) * HW));
    };
    auto conv_batch = [&](char* buf, int j0) {
#pragma unroll
        for (int j = 0; j < 5; ++j) {
            const int k = chbase + j0 + j;
            const float sc = scale_s[k], sh = shift_s[k];
            float g0 = fast_gelu(fmaf(v[j].x, sc, sh));
            float g1 = fast_gelu(fmaf(v[j].y, sc, sh));
            float g2 = fast_gelu(fmaf(v[j].z, sc, sh));
            float g3 = fast_gelu(fmaf(v[j].w, sc, sh));
            __half2 o2[2];
            o2[0] = __floats2half2_rn(g0, g1);
            o2[1] = __floats2half2_rn(g2, g3);
            *(float2*)((__half*)buf + k * PB + chunk * 4) = *(float2*)o2;
        }
    };

    // prologue: tile 0 into buf0
    issue_batch(blockIdx.x * TILES_PER_CTA, 0);
    conv_batch(smem + SM_B0, 0);
    issue_batch(blockIdx.x * TILES_PER_CTA, 5);
    conv_batch(smem + SM_B0, 5);
    __syncthreads();

    for (int t = 0; t < TILES_PER_CTA; ++t) {
        const int tile = blockIdx.x * TILES_PER_CTA + t;
        const int b = (tile * TILE_PX) / HW;
        const int p0 = tile * TILE_PX - b * HW;
        const uint32_t curbuf = (t & 1) ? SM_B1 : SM_B0;
        char* nxtbuf = smem + ((t & 1) ? SM_B0 : SM_B1);
        const bool more = (t + 1 < TILES_PER_CTA);

        // batch 0 of t+1 in flight under MMA
        if (more) issue_batch(tile + 1, 0);

        float acc[5][2][4] = {};
        mma_tile(sb, curbuf, acc, wid, lane);

        if (more) {
            conv_batch(nxtbuf, 0);          // data landed under MMA
            issue_batch(tile + 1, 5);       // batch 1 latency hides under conv+epilogue
        }

        __half* yb = g_yt + (size_t)b * CDIM * HW;

        // border zeroing: threads 0..63 own px of this tile
        if (tid < TILE_PX) {
            const int q = p0 + tid;
            const int h = q / WIMG;
            const int w = q - h * WIMG;
            const __half z = __ushort_as_half((unsigned short)0);
            if (h == WIMG - 1) { for (int c = 0;  c < 32;  ++c) yb[(size_t)c * HW + q] = z; }
            if (h == 0)        { for (int c = 32; c < 64;  ++c) yb[(size_t)c * HW + q] = z; }
            if (w == 0)        { for (int c = 64; c < 96;  ++c) yb[(size_t)c * HW + q] = z; }
            if (w == WIMG - 1) { for (int c = 96; c < 128; ++c) yb[(size_t)c * HW + q] = z; }
        }

        // epilogue: +bias -> fp16, scatter into pre-shifted yt
#pragma unroll
        for (int mi = 0; mi < 5; ++mi) {
#pragma unroll
            for (int row = 0; row < 2; ++row) {
                const int r = wm * 80 + mi * 16 + tr + row * 8;
                const float bia = bias_s[r];
                const int seg = r >> 5;
                __half* base = yb + (size_t)r * HW;
#pragma unroll
                for (int ni = 0; ni < 2; ++ni) {
                    const int c = wn * 16 + ni * 8 + tc;
                    const int q = p0 + c;
                    const int h = q / WIMG;
                    const int w = q - h * WIMG;
                    const float f0 = acc[mi][ni][row * 2 + 0] + bia;
                    const float f1 = acc[mi][ni][row * 2 + 1] + bia;
                    if (seg == 0) {          // shift up: src(h,w)->tgt(h-1,w)
                        if (h >= 1) *(__half2*)(base + q - WIMG) = __floats2half2_rn(f0, f1);
                    } else if (seg == 1) {   // shift down: ->(h+1,w)
                        if (h <= WIMG - 2) *(__half2*)(base + q + WIMG) = __floats2half2_rn(f0, f1);
                    } else if (seg == 2) {   // shift right: ->(h,w+1)
                        if (w <= WIMG - 2) base[q + 1] = __float2half_rn(f0);
                        if (w <= WIMG - 3) base[q + 2] = __float2half_rn(f1);
                    } else if (seg == 3) {   // shift left: ->(h,w-1)
                        if (w >= 1) base[q - 1] = __float2half_rn(f0);
                        base[q] = __float2half_rn(f1);
                    } else {                 // center
                        *(__half2*)(base + q) = __floats2half2_rn(f0, f1);
                    }
                }
            }
        }
        if (more) conv_batch(nxtbuf, 5);
        __syncthreads();
    }
}

// ---------------------------------------------------------------------------
// Kernel 2: out = W_fuse @ yt + b_fuse   (pure aligned 16B copies for B)
// ---------------------------------------------------------------------------
__global__ __launch_bounds__(NTHREADS, 2) void gemm2_mma(
    const float* __restrict__ Wf, const float* __restrict__ bf,
    float* __restrict__ out) {
    extern __shared__ char smem[];
    const uint32_t sb = smem_u32(smem);
    const int tid = threadIdx.x;
    const int wid = tid >> 5, lane = tid & 31;
    float* bias_s = (float*)(smem + SM_BIAS);
    __half* Aw = (__half*)(smem + SM_A);

    for (int idx = tid; idx < CDIM * CDIM; idx += NTHREADS) {
        int m = idx / CDIM;
        int k = idx - m * CDIM;
        Aw[m * PA + k] = __float2half_rn(Wf[m * CDIM + k]);
    }
    if (tid < CDIM) bias_s[tid] = bf[tid];
    __syncthreads();

    // prep mapping: slot = tid&7 (8px each), channels chbase..chbase+4
    const int slot = tid & 7;
    const int chbase = (tid >> 3) * 5;
    const int wm = wid >> 2, wn = wid & 3;
    const int tr = lane >> 2, tc = 2 * (lane & 3);

    uint4 v[5];

    auto issue_loads = [&](int tile) {
        const int b = (tile * TILE_PX) / HW;
        const int p0 = tile * TILE_PX - b * HW;
        const __half* yb = g_yt + (size_t)b * CDIM * HW + p0 + slot * 8;
#pragma unroll
        for (int j = 0; j < 5; ++j)
            v[j] = __ldg((const uint4*)(yb + (size_t)(chbase + j) * HW));
    };
    auto store_smem = [&](char* buf) {
#pragma unroll
        for (int j = 0; j < 5; ++j)
            *(uint4*)((__half*)buf + (chbase + j) * PB + slot * 8) = v[j];
    };

    issue_loads(blockIdx.x * TILES_PER_CTA);
    store_smem(smem + SM_B0);
    __syncthreads();

    for (int t = 0; t < TILES_PER_CTA; ++t) {
        const int tile = blockIdx.x * TILES_PER_CTA + t;
        const int b = (tile * TILE_PX) / HW;
        const int p0 = tile * TILE_PX - b * HW;
        const uint32_t curbuf = (t & 1) ? SM_B1 : SM_B0;
        char* nxtbuf = smem + ((t & 1) ? SM_B0 : SM_B1);

        if (t + 1 < TILES_PER_CTA) issue_loads(tile + 1);   // in flight under MMA

        float acc[5][2][4] = {};
        mma_tile(sb, curbuf, acc, wid, lane);

        if (t + 1 < TILES_PER_CTA) store_smem(nxtbuf);      // data landed under MMA

        float* ob = out + (size_t)b * CDIM * HW + p0;
#pragma unroll
        for (int mi = 0; mi < 5; ++mi) {
            const int r0 = wm * 80 + mi * 16 + tr;
            const float bia0 = bias_s[r0];
            const float bia1 = bias_s[r0 + 8];
#pragma unroll
            for (int ni = 0; ni < 2; ++ni) {
                const int c = wn * 16 + ni * 8 + tc;
                *(float2*)(ob + (size_t)r0 * HW + c) =
                    make_float2(acc[mi][ni][0] + bia0, acc[mi][ni][1] + bia0);
                *(float2*)(ob + (size_t)(r0 + 8) * HW + c) =
                    make_float2(acc[mi][ni][2] + bia1, acc[mi][ni][3] + bia1);
            }
        }
        __syncthreads();
    }
}

// ---------------------------------------------------------------------------
extern "C" void kernel_launch(void* const* d_in, const int* in_sizes, int n_in,
                              void* d_out, int out_size) {
    const float* x     = (const float*)d_in[0];
    const float* gamma = (const float*)d_in[1];
    const float* beta  = (const float*)d_in[2];
    const float* rmean = (const float*)d_in[3];
    const float* rvar  = (const float*)d_in[4];
    const float* Wt = (const float*)d_in[5];  const float* bt = (const float*)d_in[6];
    const float* Wb = (const float*)d_in[7];  const float* bb = (const float*)d_in[8];
    const float* Wr = (const float*)d_in[9];  const float* br = (const float*)d_in[10];
    const float* Wl = (const float*)d_in[11]; const float* bl = (const float*)d_in[12];
    const float* Wc = (const float*)d_in[13]; const float* bc = (const float*)d_in[14];
    const float* Wf = (const float*)d_in[15]; const float* bf = (const float*)d_in[16];

    cudaFuncSetAttribute(gemm1_mma, cudaFuncAttributeMaxDynamicSharedMemorySize, SM_TOTAL);
    cudaFuncSetAttribute(gemm2_mma, cudaFuncAttributeMaxDynamicSharedMemorySize, SM_TOTAL);

    gemm1_mma<<<NBLOCKS, NTHREADS, SM_TOTAL>>>(x, gamma, beta, rmean, rvar,
                                               Wt, bt, Wb, bb, Wr, br, Wl, bl, Wc, bc);
    gemm2_mma<<<NBLOCKS, NTHREADS, SM_TOTAL>>>(Wf, bf, (float*)d_out);
}

// round 12
// speedup vs baseline: 1.4999x; 1.0852x over previous
#include <cuda_runtime.h>
#include <cuda_fp16.h>
#include <math.h>
#include <cstdint>

#define CDIM 160
#define HW 12544
#define WIMG 112
#define NIMG 32
#define NTHREADS 256
#define TILE_PX 64
#define TILES_PER_CTA 7
#define NBLOCKS 896          // 896 * 7 * 64px = 32*12544 px

#define PA 168      // A smem pitch (fp16) -> conflict-free ldmatrix
#define PB 72       // B smem pitch (fp16) -> conflict-free ldmatrix.trans
#define PD 72       // D staging pitch (halves), aliases dead B buffer
#define BSIZE (CDIM * PB * 2)   // 23040 bytes, one B tile

// shared memory byte offsets
#define SM_BIAS  0
#define SM_SCALE 640
#define SM_SHIFT 1280
#define SM_A     2048                       // 160*168*2 = 53760
#define SM_B0    (SM_A + CDIM * PA * 2)     // 55808
#define SM_B1    (SM_B0 + BSIZE)            // 78848
#define SM_TOTAL (SM_B1 + BSIZE)            // 101888 (2 CTAs/SM)

// PRE-SHIFTED intermediate: yt[c][p] = (shifted y)[c][p], channel-major fp16.
__device__ __half g_yt[(size_t)NIMG * CDIM * HW + 16];

// ---------------------------------------------------------------------------
__device__ __forceinline__ uint32_t smem_u32(const void* p) {
    uint32_t a;
    asm("{ .reg .u64 t; cvta.to.shared.u64 t, %1; cvt.u32.u64 %0, t; }" : "=r"(a) : "l"(p));
    return a;
}
__device__ __forceinline__ void ldsm_x4(uint32_t* r, uint32_t addr) {
    asm volatile("ldmatrix.sync.aligned.m8n8.x4.shared.b16 {%0,%1,%2,%3}, [%4];"
        : "=r"(r[0]), "=r"(r[1]), "=r"(r[2]), "=r"(r[3]) : "r"(addr));
}
__device__ __forceinline__ void ldsm_x4t(uint32_t* r, uint32_t addr) {
    asm volatile("ldmatrix.sync.aligned.m8n8.x4.trans.shared.b16 {%0,%1,%2,%3}, [%4];"
        : "=r"(r[0]), "=r"(r[1]), "=r"(r[2]), "=r"(r[3]) : "r"(addr));
}
__device__ __forceinline__ void mma16816(float* d, const uint32_t* a, const uint32_t* b) {
    asm volatile("mma.sync.aligned.m16n8k16.row.col.f32.f16.f16.f32 "
        "{%0,%1,%2,%3}, {%4,%5,%6,%7}, {%8,%9}, {%0,%1,%2,%3};"
        : "+f"(d[0]), "+f"(d[1]), "+f"(d[2]), "+f"(d[3])
        : "r"(a[0]), "r"(a[1]), "r"(a[2]), "r"(a[3]), "r"(b[0]), "r"(b[1]));
}

// fast exact-GELU: erf via Abramowitz-Stegun 7.1.26, |abs err| <= 1.5e-7
__device__ __forceinline__ float fast_gelu(float h) {
    const float x = h * 0.70710678118654752f;
    const float ax = fabsf(x);
    const float t = __fdividef(1.0f, fmaf(0.3275911f, ax, 1.0f));
    float p = fmaf(t, 1.061405429f, -1.453152027f);
    p = fmaf(t, p, 1.421413741f);
    p = fmaf(t, p, -0.284496736f);
    p = fmaf(t, p, 0.254829592f);
    p *= t;
    const float e = __expf(-ax * ax);
    const float erf_abs = fmaf(-p, e, 1.0f);
    const float erf_v = copysignf(erf_abs, x);
    return 0.5f * h * (1.0f + erf_v);
}

// ---------------------------------------------------------------------------
// 1-pass fp16 MMA over a 160(ch) x 64(px) tile. 8 warps: 2M x 4N.
// ---------------------------------------------------------------------------
__device__ __forceinline__ void mma_tile(uint32_t sb, uint32_t bufbase,
                                         float acc[5][2][4], int wid, int lane) {
    const int wm = wid >> 2, wn = wid & 3;
    const uint32_t a_lane = (uint32_t)((wm * 80 + (lane & 15)) * (PA * 2) + (lane >> 4) * 16);
    const uint32_t b_lane = (uint32_t)((lane & 15) * (PB * 2) + (wn * 16 + (lane >> 4) * 8) * 2);
    const uint32_t Ab = sb + SM_A + a_lane;
    const uint32_t Bb = sb + bufbase + b_lane;

#pragma unroll
    for (int k0 = 0; k0 < CDIM; k0 += 16) {
        uint32_t a[5][4];
#pragma unroll
        for (int mi = 0; mi < 5; ++mi)
            ldsm_x4(a[mi], Ab + mi * 16 * (PA * 2) + k0 * 2);
        uint32_t b[4];
        ldsm_x4t(b, Bb + k0 * (PB * 2));
#pragma unroll
        for (int mi = 0; mi < 5; ++mi) {
            mma16816(acc[mi][0], a[mi], b);
            mma16816(acc[mi][1], a[mi], b + 2);
        }
    }
}

// ---------------------------------------------------------------------------
// Kernel 1: yt = scatter_shift( W_cat @ gelu(bn(x)) + b_cat )
// ---------------------------------------------------------------------------
__global__ __launch_bounds__(NTHREADS, 2) void gemm1_mma(
    const float* __restrict__ x,
    const float* __restrict__ gamma, const float* __restrict__ beta,
    const float* __restrict__ rmean, const float* __restrict__ rvar,
    const float* __restrict__ Wt, const float* __restrict__ bt,
    const float* __restrict__ Wb, const float* __restrict__ bb,
    const float* __restrict__ Wr, const float* __restrict__ br,
    const float* __restrict__ Wl, const float* __restrict__ bl,
    const float* __restrict__ Wc, const float* __restrict__ bc) {
    extern __shared__ char smem[];
    const uint32_t sb = smem_u32(smem);
    const int tid = threadIdx.x;
    const int wid = tid >> 5, lane = tid & 31;
    float* bias_s  = (float*)(smem + SM_BIAS);
    float* scale_s = (float*)(smem + SM_SCALE);
    float* shift_s = (float*)(smem + SM_SHIFT);
    __half* Aw = (__half*)(smem + SM_A);

    const float* Wseg[5] = {Wt, Wb, Wr, Wl, Wc};
    for (int idx = tid; idx < CDIM * CDIM; idx += NTHREADS) {
        int m = idx / CDIM;
        int k = idx - m * CDIM;
        Aw[m * PA + k] = __float2half_rn(Wseg[m >> 5][(m & 31) * CDIM + k]);
    }
    if (tid < CDIM) {
        const float* bp[5] = {bt, bb, br, bl, bc};
        bias_s[tid] = bp[tid >> 5][tid & 31];
        float s = gamma[tid] * rsqrtf(rvar[tid] + 1e-5f);
        scale_s[tid] = s;
        shift_s[tid] = beta[tid] - rmean[tid] * s;
    }
    __syncthreads();

    // prep mapping: chunk = tid&15 (4px each), channels chbase..chbase+9
    const int chunk = tid & 15;
    const int chbase = (tid >> 4) * 10;
    const int wm = wid >> 2, wn = wid & 3;
    const int tr = lane >> 2, tc = 2 * (lane & 3);

    float4 v[5];

    auto issue_batch = [&](int tile, int j0) {
        const int b = (tile * TILE_PX) / HW;
        const int p0 = tile * TILE_PX - b * HW;
        const float* xb = x + (size_t)b * CDIM * HW + p0 + chunk * 4;
#pragma unroll
        for (int j = 0; j < 5; ++j)
            v[j] = __ldg((const float4*)(xb + (size_t)(chbase + j0 + j) * HW));
    };
    auto conv_batch = [&](char* buf, int j0) {
#pragma unroll
        for (int j = 0; j < 5; ++j) {
            const int k = chbase + j0 + j;
            const float sc = scale_s[k], sh = shift_s[k];
            float g0 = fast_gelu(fmaf(v[j].x, sc, sh));
            float g1 = fast_gelu(fmaf(v[j].y, sc, sh));
            float g2 = fast_gelu(fmaf(v[j].z, sc, sh));
            float g3 = fast_gelu(fmaf(v[j].w, sc, sh));
            __half2 o2[2];
            o2[0] = __floats2half2_rn(g0, g1);
            o2[1] = __floats2half2_rn(g2, g3);
            *(float2*)((__half*)buf + k * PB + chunk * 4) = *(float2*)o2;
        }
    };

    // prologue: tile 0 into buf0
    issue_batch(blockIdx.x * TILES_PER_CTA, 0);
    conv_batch(smem + SM_B0, 0);
    issue_batch(blockIdx.x * TILES_PER_CTA, 5);
    conv_batch(smem + SM_B0, 5);
    __syncthreads();

    for (int t = 0; t < TILES_PER_CTA; ++t) {
        const int tile = blockIdx.x * TILES_PER_CTA + t;
        const int b = (tile * TILE_PX) / HW;
        const int p0 = tile * TILE_PX - b * HW;
        const uint32_t curbuf = (t & 1) ? SM_B1 : SM_B0;
        char* nxtbuf = smem + ((t & 1) ? SM_B0 : SM_B1);
        const bool more = (t + 1 < TILES_PER_CTA);

        // batch 0 of t+1 in flight under MMA
        if (more) issue_batch(tile + 1, 0);

        float acc[5][2][4] = {};
        mma_tile(sb, curbuf, acc, wid, lane);

        if (more) {
            conv_batch(nxtbuf, 0);          // data landed under MMA
            issue_batch(tile + 1, 5);       // batch 1 latency hides under staging
        }
        __syncthreads();                    // all curbuf reads done

        // stage D (+bias -> fp16) into the dead current B buffer
        {
            __half* Dst = (__half*)(smem + curbuf);
#pragma unroll
            for (int mi = 0; mi < 5; ++mi) {
#pragma unroll
                for (int row = 0; row < 2; ++row) {
                    const int r = wm * 80 + mi * 16 + row * 8 + tr;
                    const float bia = bias_s[r];
                    *(__half2*)(Dst + r * PD + wn * 16 + tc) =
                        __floats2half2_rn(acc[mi][0][row * 2 + 0] + bia,
                                          acc[mi][0][row * 2 + 1] + bia);
                    *(__half2*)(Dst + r * PD + wn * 16 + 8 + tc) =
                        __floats2half2_rn(acc[mi][1][row * 2 + 0] + bia,
                                          acc[mi][1][row * 2 + 1] + bia);
                }
            }
        }
        __syncthreads();                    // staging complete

        // write-out by 8-px spans: 1280 spans, 5 per thread.
        // Rows are 112=14*8 px, so a span never crosses an image row.
        {
            const __half* Dst = (const __half*)(smem + curbuf);
            __half* yb = g_yt + (size_t)b * CDIM * HW;
#pragma unroll
            for (int i = 0; i < 5; ++i) {
                const int item = i * NTHREADS + tid;
                const int ch = item >> 3;
                const int sp = item & 7;
                const int q = p0 + sp * 8;
                const int h = q / WIMG;
                const int w0 = q - h * WIMG;        // in {0,8,...,104}
                const int seg = ch >> 5;
                const uint4 v4 = *(const uint4*)(Dst + ch * PD + sp * 8);
                __half* base = yb + (size_t)ch * HW;
                if (seg == 0) {                     // shift up: y[q] -> yt[q-112]
                    if (h > 0) *(uint4*)(base + q - WIMG) = v4;
                    else       *(uint4*)(base + q + (WIMG - 1) * WIMG) = make_uint4(0, 0, 0, 0);
                } else if (seg == 1) {              // shift down: -> yt[q+112]
                    if (h < WIMG - 1) *(uint4*)(base + q + WIMG) = v4;
                    else              *(uint4*)(base + q - (WIMG - 1) * WIMG) = make_uint4(0, 0, 0, 0);
                } else if (seg == 2) {              // yt[p]=y[p-1]: y[q..q+7] -> yt[q+1..q+8]
                    const uint32_t pa = (v4.x >> 16) | (v4.y << 16);   // (y1,y2)
                    const uint32_t pb = (v4.y >> 16) | (v4.z << 16);   // (y3,y4)
                    const uint32_t pc = (v4.z >> 16) | (v4.w << 16);   // (y5,y6)
                    *(uint16_t*)(base + q + 1) = (uint16_t)(v4.x & 0xFFFFu);
                    *(uint32_t*)(base + q + 2) = pa;
                    *(uint32_t*)(base + q + 4) = pb;
                    *(uint32_t*)(base + q + 6) = pc;
                    if (w0 < 104) *(uint16_t*)(base + q + 8) = (uint16_t)(v4.w >> 16);
                    if (w0 == 0)  *(uint16_t*)(base + q) = 0;          // yt[w=0]=0
                } else if (seg == 3) {              // yt[p]=y[p+1]: y[q..q+7] -> yt[q-1..q+6]
                    const uint32_t pa = (v4.x >> 16) | (v4.y << 16);   // (y1,y2)
                    const uint32_t pb = (v4.y >> 16) | (v4.z << 16);   // (y3,y4)
                    const uint32_t pc = (v4.z >> 16) | (v4.w << 16);   // (y5,y6)
                    if (w0 > 0) *(uint16_t*)(base + q - 1) = (uint16_t)(v4.x & 0xFFFFu);
                    *(uint32_t*)(base + q)     = pa;
                    *(uint32_t*)(base + q + 2) = pb;
                    *(uint32_t*)(base + q + 4) = pc;
                    *(uint16_t*)(base + q + 6) = (uint16_t)(v4.w >> 16);
                    if (w0 == 104) *(uint16_t*)(base + q + 7) = 0;     // yt[w=111]=0
                } else {                            // center
                    *(uint4*)(base + q) = v4;
                }
            }
        }

        if (more) conv_batch(nxtbuf, 5);
        __syncthreads();                    // tile end: nxtbuf ready, Dst reads done
    }
}

// ---------------------------------------------------------------------------
// Kernel 2: out = W_fuse @ yt + b_fuse   (pure aligned 16B copies for B)
// ---------------------------------------------------------------------------
__global__ __launch_bounds__(NTHREADS, 2) void gemm2_mma(
    const float* __restrict__ Wf, const float* __restrict__ bf,
    float* __restrict__ out) {
    extern __shared__ char smem[];
    const uint32_t sb = smem_u32(smem);
    const int tid = threadIdx.x;
    const int wid = tid >> 5, lane = tid & 31;
    float* bias_s = (float*)(smem + SM_BIAS);
    __half* Aw = (__half*)(smem + SM_A);

    for (int idx = tid; idx < CDIM * CDIM; idx += NTHREADS) {
        int m = idx / CDIM;
        int k = idx - m * CDIM;
        Aw[m * PA + k] = __float2half_rn(Wf[m * CDIM + k]);
    }
    if (tid < CDIM) bias_s[tid] = bf[tid];
    __syncthreads();

    // prep mapping: slot = tid&7 (8px each), channels chbase..chbase+4
    const int slot = tid & 7;
    const int chbase = (tid >> 3) * 5;
    const int wm = wid >> 2, wn = wid & 3;
    const int tr = lane >> 2, tc = 2 * (lane & 3);

    uint4 v[5];

    auto issue_loads = [&](int tile) {
        const int b = (tile * TILE_PX) / HW;
        const int p0 = tile * TILE_PX - b * HW;
        const __half* yb = g_yt + (size_t)b * CDIM * HW + p0 + slot * 8;
#pragma unroll
        for (int j = 0; j < 5; ++j)
            v[j] = __ldg((const uint4*)(yb + (size_t)(chbase + j) * HW));
    };
    auto store_smem = [&](char* buf) {
#pragma unroll
        for (int j = 0; j < 5; ++j)
            *(uint4*)((__half*)buf + (chbase + j) * PB + slot * 8) = v[j];
    };

    issue_loads(blockIdx.x * TILES_PER_CTA);
    store_smem(smem + SM_B0);
    __syncthreads();

    for (int t = 0; t < TILES_PER_CTA; ++t) {
        const int tile = blockIdx.x * TILES_PER_CTA + t;
        const int b = (tile * TILE_PX) / HW;
        const int p0 = tile * TILE_PX - b * HW;
        const uint32_t curbuf = (t & 1) ? SM_B1 : SM_B0;
        char* nxtbuf = smem + ((t & 1) ? SM_B0 : SM_B1);

        if (t + 1 < TILES_PER_CTA) issue_loads(tile + 1);   // in flight under MMA

        float acc[5][2][4] = {};
        mma_tile(sb, curbuf, acc, wid, lane);

        if (t + 1 < TILES_PER_CTA) store_smem(nxtbuf);      // data landed under MMA

        float* ob = out + (size_t)b * CDIM * HW + p0;
#pragma unroll
        for (int mi = 0; mi < 5; ++mi) {
            const int r0 = wm * 80 + mi * 16 + tr;
            const float bia0 = bias_s[r0];
            const float bia1 = bias_s[r0 + 8];
#pragma unroll
            for (int ni = 0; ni < 2; ++ni) {
                const int c = wn * 16 + ni * 8 + tc;
                *(float2*)(ob + (size_t)r0 * HW + c) =
                    make_float2(acc[mi][ni][0] + bia0, acc[mi][ni][1] + bia0);
                *(float2*)(ob + (size_t)(r0 + 8) * HW + c) =
                    make_float2(acc[mi][ni][2] + bia1, acc[mi][ni][3] + bia1);
            }
        }
        __syncthreads();
    }
}

// ---------------------------------------------------------------------------
extern "C" void kernel_launch(void* const* d_in, const int* in_sizes, int n_in,
                              void* d_out, int out_size) {
    const float* x     = (const float*)d_in[0];
    const float* gamma = (const float*)d_in[1];
    const float* beta  = (const float*)d_in[2];
    const float* rmean = (const float*)d_in[3];
    const float* rvar  = (const float*)d_in[4];
    const float* Wt = (const float*)d_in[5];  const float* bt = (const float*)d_in[6];
    const float* Wb = (const float*)d_in[7];  const float* bb = (const float*)d_in[8];
    const float* Wr = (const float*)d_in[9];  const float* br = (const float*)d_in[10];
    const float* Wl = (const float*)d_in[11]; const float* bl = (const float*)d_in[12];
    const float* Wc = (const float*)d_in[13]; const float* bc = (const float*)d_in[14];
    const float* Wf = (const float*)d_in[15]; const float* bf = (const float*)d_in[16];

    cudaFuncSetAttribute(gemm1_mma, cudaFuncAttributeMaxDynamicSharedMemorySize, SM_TOTAL);
    cudaFuncSetAttribute(gemm2_mma, cudaFuncAttributeMaxDynamicSharedMemorySize, SM_TOTAL);

    gemm1_mma<<<NBLOCKS, NTHREADS, SM_TOTAL>>>(x, gamma, beta, rmean, rvar,
                                               Wt, bt, Wb, bb, Wr, br, Wl, bl, Wc, bc);
    gemm2_mma<<<NBLOCKS, NTHREADS, SM_TOTAL>>>(Wf, bf, (float*)d_out);
}

// round 13
// speedup vs baseline: 1.5305x; 1.0204x over previous
#include <cuda_runtime.h>
#include <cuda_fp16.h>
#include <math.h>
#include <cstdint>

#define CDIM 160
#define HW 12544
#define WIMG 112
#define NIMG 32
#define NTHREADS 256
#define TILE_PX 64
#define TILES_PER_CTA 7
#define NBLOCKS 896          // 896 * 7 * 64px = 32*12544 px

#define PA 168      // A smem pitch (fp16) -> conflict-free ldmatrix
#define PB 72       // B smem pitch (fp16) -> conflict-free ldmatrix.trans
#define PD 72       // D staging pitch (halves), aliases dead B buffer
#define BSIZE (CDIM * PB * 2)   // 23040 bytes, one B tile

// shared memory byte offsets
#define SM_BIAS  0
#define SM_SCALE 640
#define SM_SHIFT 1280
#define SM_A     2048                       // 160*168*2 = 53760
#define SM_B0    (SM_A + CDIM * PA * 2)     // 55808
#define SM_B1    (SM_B0 + BSIZE)            // 78848
#define SM_TOTAL (SM_B1 + BSIZE)            // 101888 (2 CTAs/SM)

// PRE-SHIFTED intermediate: yt[c][p] = (shifted y)[c][p], channel-major fp16.
__device__ __half g_yt[(size_t)NIMG * CDIM * HW + 16];

// ---------------------------------------------------------------------------
__device__ __forceinline__ uint32_t smem_u32(const void* p) {
    uint32_t a;
    asm("{ .reg .u64 t; cvta.to.shared.u64 t, %1; cvt.u32.u64 %0, t; }" : "=r"(a) : "l"(p));
    return a;
}
__device__ __forceinline__ void ldsm_x4(uint32_t* r, uint32_t addr) {
    asm volatile("ldmatrix.sync.aligned.m8n8.x4.shared.b16 {%0,%1,%2,%3}, [%4];"
        : "=r"(r[0]), "=r"(r[1]), "=r"(r[2]), "=r"(r[3]) : "r"(addr));
}
__device__ __forceinline__ void ldsm_x4t(uint32_t* r, uint32_t addr) {
    asm volatile("ldmatrix.sync.aligned.m8n8.x4.trans.shared.b16 {%0,%1,%2,%3}, [%4];"
        : "=r"(r[0]), "=r"(r[1]), "=r"(r[2]), "=r"(r[3]) : "r"(addr));
}
__device__ __forceinline__ void mma16816(float* d, const uint32_t* a, const uint32_t* b) {
    asm volatile("mma.sync.aligned.m16n8k16.row.col.f32.f16.f16.f32 "
        "{%0,%1,%2,%3}, {%4,%5,%6,%7}, {%8,%9}, {%0,%1,%2,%3};"
        : "+f"(d[0]), "+f"(d[1]), "+f"(d[2]), "+f"(d[3])
        : "r"(a[0]), "r"(a[1]), "r"(a[2]), "r"(a[3]), "r"(b[0]), "r"(b[1]));
}
__device__ __forceinline__ void cp_async16(uint32_t saddr, const void* gptr) {
    asm volatile("cp.async.cg.shared.global [%0], [%1], 16;" :: "r"(saddr), "l"(gptr));
}
#define CP_COMMIT() asm volatile("cp.async.commit_group;" ::: "memory")
#define CP_WAIT0()  asm volatile("cp.async.wait_group 0;" ::: "memory")

// fast exact-GELU: erf via Abramowitz-Stegun 7.1.26, |abs err| <= 1.5e-7
__device__ __forceinline__ float fast_gelu(float h) {
    const float x = h * 0.70710678118654752f;
    const float ax = fabsf(x);
    const float t = __fdividef(1.0f, fmaf(0.3275911f, ax, 1.0f));
    float p = fmaf(t, 1.061405429f, -1.453152027f);
    p = fmaf(t, p, 1.421413741f);
    p = fmaf(t, p, -0.284496736f);
    p = fmaf(t, p, 0.254829592f);
    p *= t;
    const float e = __expf(-ax * ax);
    const float erf_abs = fmaf(-p, e, 1.0f);
    const float erf_v = copysignf(erf_abs, x);
    return 0.5f * h * (1.0f + erf_v);
}

// ---------------------------------------------------------------------------
// Kernel 1: yt = scatter_shift( W_cat @ gelu(bn(x)) + b_cat )
// Conversion of next tile's first batch is interleaved INTO the MMA k-loop.
// ---------------------------------------------------------------------------
__global__ __launch_bounds__(NTHREADS, 2) void gemm1_mma(
    const float* __restrict__ x,
    const float* __restrict__ gamma, const float* __restrict__ beta,
    const float* __restrict__ rmean, const float* __restrict__ rvar,
    const float* __restrict__ Wt, const float* __restrict__ bt,
    const float* __restrict__ Wb, const float* __restrict__ bb,
    const float* __restrict__ Wr, const float* __restrict__ br,
    const float* __restrict__ Wl, const float* __restrict__ bl,
    const float* __restrict__ Wc, const float* __restrict__ bc) {
    extern __shared__ char smem[];
    const uint32_t sb = smem_u32(smem);
    const int tid = threadIdx.x;
    const int wid = tid >> 5, lane = tid & 31;
    float* bias_s  = (float*)(smem + SM_BIAS);
    float* scale_s = (float*)(smem + SM_SCALE);
    float* shift_s = (float*)(smem + SM_SHIFT);
    __half* Aw = (__half*)(smem + SM_A);

    const float* Wseg[5] = {Wt, Wb, Wr, Wl, Wc};
    for (int idx = tid; idx < CDIM * CDIM; idx += NTHREADS) {
        int m = idx / CDIM;
        int k = idx - m * CDIM;
        Aw[m * PA + k] = __float2half_rn(Wseg[m >> 5][(m & 31) * CDIM + k]);
    }
    if (tid < CDIM) {
        const float* bp[5] = {bt, bb, br, bl, bc};
        bias_s[tid] = bp[tid >> 5][tid & 31];
        float s = gamma[tid] * rsqrtf(rvar[tid] + 1e-5f);
        scale_s[tid] = s;
        shift_s[tid] = beta[tid] - rmean[tid] * s;
    }
    __syncthreads();

    // prep mapping: chunk = tid&15 (4px each), channels chbase..chbase+9
    const int chunk = tid & 15;
    const int chbase = (tid >> 4) * 10;
    const int wm = wid >> 2, wn = wid & 3;
    const int tr = lane >> 2, tc = 2 * (lane & 3);

    // MMA lane addresses
    const uint32_t a_lane = (uint32_t)((wm * 80 + (lane & 15)) * (PA * 2) + (lane >> 4) * 16);
    const uint32_t b_lane = (uint32_t)((lane & 15) * (PB * 2) + (wn * 16 + (lane >> 4) * 8) * 2);
    const uint32_t Ab = sb + SM_A + a_lane;

    float4 v[5];

    auto issue_batch = [&](int tile, int j0) {
        const int b = (tile * TILE_PX) / HW;
        const int p0 = tile * TILE_PX - b * HW;
        const float* xb = x + (size_t)b * CDIM * HW + p0 + chunk * 4;
#pragma unroll
        for (int j = 0; j < 5; ++j)
            v[j] = __ldg((const float4*)(xb + (size_t)(chbase + j0 + j) * HW));
    };
    auto conv_one = [&](char* buf, int j, int j0) {
        const int k = chbase + j0 + j;
        const float sc = scale_s[k], sh = shift_s[k];
        float g0 = fast_gelu(fmaf(v[j].x, sc, sh));
        float g1 = fast_gelu(fmaf(v[j].y, sc, sh));
        float g2 = fast_gelu(fmaf(v[j].z, sc, sh));
        float g3 = fast_gelu(fmaf(v[j].w, sc, sh));
        __half2 o2[2];
        o2[0] = __floats2half2_rn(g0, g1);
        o2[1] = __floats2half2_rn(g2, g3);
        *(float2*)((__half*)buf + k * PB + chunk * 4) = *(float2*)o2;
    };

    // prologue: tile 0 into buf0
    issue_batch(blockIdx.x * TILES_PER_CTA, 0);
#pragma unroll
    for (int j = 0; j < 5; ++j) conv_one(smem + SM_B0, j, 0);
    issue_batch(blockIdx.x * TILES_PER_CTA, 5);
#pragma unroll
    for (int j = 0; j < 5; ++j) conv_one(smem + SM_B0, j, 5);
    __syncthreads();

    for (int t = 0; t < TILES_PER_CTA; ++t) {
        const int tile = blockIdx.x * TILES_PER_CTA + t;
        const int b = (tile * TILE_PX) / HW;
        const int p0 = tile * TILE_PX - b * HW;
        const uint32_t curbuf = (t & 1) ? SM_B1 : SM_B0;
        char* nxtbuf = smem + ((t & 1) ? SM_B0 : SM_B1);
        const bool more = (t + 1 < TILES_PER_CTA);

        // batch 0 of t+1 in flight before MMA
        if (more) issue_batch(tile + 1, 0);

        // MMA with interleaved conversion of batch 0 (fills HMMA rt gaps)
        float acc[5][2][4] = {};
        const uint32_t Bb = sb + curbuf + b_lane;
#pragma unroll
        for (int kk = 0; kk < 10; ++kk) {
            const int k0 = kk * 16;
            uint32_t a[5][4];
#pragma unroll
            for (int mi = 0; mi < 5; ++mi)
                ldsm_x4(a[mi], Ab + mi * 16 * (PA * 2) + k0 * 2);
            uint32_t bfr[4];
            ldsm_x4t(bfr, Bb + k0 * (PB * 2));
#pragma unroll
            for (int mi = 0; mi < 5; ++mi) {
                mma16816(acc[mi][0], a[mi], bfr);
                mma16816(acc[mi][1], a[mi], bfr + 2);
            }
            if (more && (kk & 1)) conv_one(nxtbuf, kk >> 1, 0);
        }

        if (more) issue_batch(tile + 1, 5);   // batch 1 latency hides under staging
        __syncthreads();                      // all curbuf reads done

        // stage D (+bias -> fp16) into the dead current B buffer
        {
            __half* Dst = (__half*)(smem + curbuf);
#pragma unroll
            for (int mi = 0; mi < 5; ++mi) {
#pragma unroll
                for (int row = 0; row < 2; ++row) {
                    const int r = wm * 80 + mi * 16 + row * 8 + tr;
                    const float bia = bias_s[r];
                    *(__half2*)(Dst + r * PD + wn * 16 + tc) =
                        __floats2half2_rn(acc[mi][0][row * 2 + 0] + bia,
                                          acc[mi][0][row * 2 + 1] + bia);
                    *(__half2*)(Dst + r * PD + wn * 16 + 8 + tc) =
                        __floats2half2_rn(acc[mi][1][row * 2 + 0] + bia,
                                          acc[mi][1][row * 2 + 1] + bia);
                }
            }
        }
        __syncthreads();                    // staging complete

        // write-out by 8-px spans: 1280 spans, 5 per thread.
        {
            const __half* Dst = (const __half*)(smem + curbuf);
            __half* yb = g_yt + (size_t)b * CDIM * HW;
#pragma unroll
            for (int i = 0; i < 5; ++i) {
                const int item = i * NTHREADS + tid;
                const int ch = item >> 3;
                const int sp = item & 7;
                const int q = p0 + sp * 8;
                const int h = q / WIMG;
                const int w0 = q - h * WIMG;        // in {0,8,...,104}
                const int seg = ch >> 5;
                const uint4 v4 = *(const uint4*)(Dst + ch * PD + sp * 8);
                __half* base = yb + (size_t)ch * HW;
                if (seg == 0) {                     // shift up: y[q] -> yt[q-112]
                    if (h > 0) *(uint4*)(base + q - WIMG) = v4;
                    else       *(uint4*)(base + q + (WIMG - 1) * WIMG) = make_uint4(0, 0, 0, 0);
                } else if (seg == 1) {              // shift down: -> yt[q+112]
                    if (h < WIMG - 1) *(uint4*)(base + q + WIMG) = v4;
                    else              *(uint4*)(base + q - (WIMG - 1) * WIMG) = make_uint4(0, 0, 0, 0);
                } else if (seg == 2) {              // yt[p]=y[p-1]
                    const uint32_t pa = (v4.x >> 16) | (v4.y << 16);
                    const uint32_t pb = (v4.y >> 16) | (v4.z << 16);
                    const uint32_t pc = (v4.z >> 16) | (v4.w << 16);
                    *(uint16_t*)(base + q + 1) = (uint16_t)(v4.x & 0xFFFFu);
                    *(uint32_t*)(base + q + 2) = pa;
                    *(uint32_t*)(base + q + 4) = pb;
                    *(uint32_t*)(base + q + 6) = pc;
                    if (w0 < 104) *(uint16_t*)(base + q + 8) = (uint16_t)(v4.w >> 16);
                    if (w0 == 0)  *(uint16_t*)(base + q) = 0;
                } else if (seg == 3) {              // yt[p]=y[p+1]
                    const uint32_t pa = (v4.x >> 16) | (v4.y << 16);
                    const uint32_t pb = (v4.y >> 16) | (v4.z << 16);
                    const uint32_t pc = (v4.z >> 16) | (v4.w << 16);
                    if (w0 > 0) *(uint16_t*)(base + q - 1) = (uint16_t)(v4.x & 0xFFFFu);
                    *(uint32_t*)(base + q)     = pa;
                    *(uint32_t*)(base + q + 2) = pb;
                    *(uint32_t*)(base + q + 4) = pc;
                    *(uint16_t*)(base + q + 6) = (uint16_t)(v4.w >> 16);
                    if (w0 == 104) *(uint16_t*)(base + q + 7) = 0;
                } else {                            // center
                    *(uint4*)(base + q) = v4;
                }
            }
        }

        if (more) {
#pragma unroll
            for (int j = 0; j < 5; ++j) conv_one(nxtbuf, j, 5);
        }
        __syncthreads();                    // tile end
    }
}

// ---------------------------------------------------------------------------
// Kernel 2: out = W_fuse @ yt + b_fuse   (cp.async 16B prefetch for B)
// ---------------------------------------------------------------------------
__global__ __launch_bounds__(NTHREADS, 2) void gemm2_mma(
    const float* __restrict__ Wf, const float* __restrict__ bf,
    float* __restrict__ out) {
    extern __shared__ char smem[];
    const uint32_t sb = smem_u32(smem);
    const int tid = threadIdx.x;
    const int wid = tid >> 5, lane = tid & 31;
    float* bias_s = (float*)(smem + SM_BIAS);
    __half* Aw = (__half*)(smem + SM_A);

    for (int idx = tid; idx < CDIM * CDIM; idx += NTHREADS) {
        int m = idx / CDIM;
        int k = idx - m * CDIM;
        Aw[m * PA + k] = __float2half_rn(Wf[m * CDIM + k]);
    }
    if (tid < CDIM) bias_s[tid] = bf[tid];
    __syncthreads();

    // prep mapping: slot = tid&7 (8px each), channels chbase..chbase+4
    const int slot = tid & 7;
    const int chbase = (tid >> 3) * 5;
    const int wm = wid >> 2, wn = wid & 3;
    const int tr = lane >> 2, tc = 2 * (lane & 3);

    const uint32_t a_lane = (uint32_t)((wm * 80 + (lane & 15)) * (PA * 2) + (lane >> 4) * 16);
    const uint32_t b_lane = (uint32_t)((lane & 15) * (PB * 2) + (wn * 16 + (lane >> 4) * 8) * 2);
    const uint32_t Ab = sb + SM_A + a_lane;

    auto issue_cp = [&](int tile, uint32_t bufoff) {
        const int b = (tile * TILE_PX) / HW;
        const int p0 = tile * TILE_PX - b * HW;
        const __half* yb = g_yt + (size_t)b * CDIM * HW + p0 + slot * 8;
#pragma unroll
        for (int j = 0; j < 5; ++j)
            cp_async16(sb + bufoff + (uint32_t)(((chbase + j) * PB + slot * 8) * 2),
                       yb + (size_t)(chbase + j) * HW);
        CP_COMMIT();
    };

    issue_cp(blockIdx.x * TILES_PER_CTA, SM_B0);
    CP_WAIT0();
    __syncthreads();

    for (int t = 0; t < TILES_PER_CTA; ++t) {
        const int tile = blockIdx.x * TILES_PER_CTA + t;
        const int b = (tile * TILE_PX) / HW;
        const int p0 = tile * TILE_PX - b * HW;
        const uint32_t curbuf = (t & 1) ? SM_B1 : SM_B0;
        const uint32_t nxtoff = (t & 1) ? SM_B0 : SM_B1;

        if (t + 1 < TILES_PER_CTA) issue_cp(tile + 1, nxtoff);  // async under MMA

        float acc[5][2][4] = {};
        const uint32_t Bb = sb + curbuf + b_lane;
#pragma unroll
        for (int kk = 0; kk < 10; ++kk) {
            const int k0 = kk * 16;
            uint32_t a[5][4];
#pragma unroll
            for (int mi = 0; mi < 5; ++mi)
                ldsm_x4(a[mi], Ab + mi * 16 * (PA * 2) + k0 * 2);
            uint32_t bfr[4];
            ldsm_x4t(bfr, Bb + k0 * (PB * 2));
#pragma unroll
            for (int mi = 0; mi < 5; ++mi) {
                mma16816(acc[mi][0], a[mi], bfr);
                mma16816(acc[mi][1], a[mi], bfr + 2);
            }
        }

        CP_WAIT0();                                  // next tile landed

        float* ob = out + (size_t)b * CDIM * HW + p0;
#pragma unroll
        for (int mi = 0; mi < 5; ++mi) {
            const int r0 = wm * 80 + mi * 16 + tr;
            const float bia0 = bias_s[r0];
            const float bia1 = bias_s[r0 + 8];
#pragma unroll
            for (int ni = 0; ni < 2; ++ni) {
                const int c = wn * 16 + ni * 8 + tc;
                *(float2*)(ob + (size_t)r0 * HW + c) =
                    make_float2(acc[mi][ni][0] + bia0, acc[mi][ni][1] + bia0);
                *(float2*)(ob + (size_t)(r0 + 8) * HW + c) =
                    make_float2(acc[mi][ni][2] + bia1, acc[mi][ni][3] + bia1);
            }
        }
        __syncthreads();
    }
}

// ---------------------------------------------------------------------------
extern "C" void kernel_launch(void* const* d_in, const int* in_sizes, int n_in,
                              void* d_out, int out_size) {
    const float* x     = (const float*)d_in[0];
    const float* gamma = (const float*)d_in[1];
    const float* beta  = (const float*)d_in[2];
    const float* rmean = (const float*)d_in[3];
    const float* rvar  = (const float*)d_in[4];
    const float* Wt = (const float*)d_in[5];  const float* bt = (const float*)d_in[6];
    const float* Wb = (const float*)d_in[7];  const float* bb = (const float*)d_in[8];
    const float* Wr = (const float*)d_in[9];  const float* br = (const float*)d_in[10];
    const float* Wl = (const float*)d_in[11]; const float* bl = (const float*)d_in[12];
    const float* Wc = (const float*)d_in[13]; const float* bc = (const float*)d_in[14];
    const float* Wf = (const float*)d_in[15]; const float* bf = (const float*)d_in[16];

    cudaFuncSetAttribute(gemm1_mma, cudaFuncAttributeMaxDynamicSharedMemorySize, SM_TOTAL);
    cudaFuncSetAttribute(gemm2_mma, cudaFuncAttributeMaxDynamicSharedMemorySize, SM_TOTAL);

    gemm1_mma<<<NBLOCKS, NTHREADS, SM_TOTAL>>>(x, gamma, beta, rmean, rvar,
                                               Wt, bt, Wb, bb, Wr, br, Wl, bl, Wc, bc);
    gemm2_mma<<<NBLOCKS, NTHREADS, SM_TOTAL>>>(Wf, bf, (float*)d_out);
}